// round 2
// baseline (speedup 1.0000x reference)
#include <cuda_runtime.h>
#include <cuda_bf16.h>
#include <stdint.h>

#define NTOK 8192
#define DHALF 64
#define DE 128
#define BM 64
#define BN 64
#define QSTR 132   // fp32 row stride for Q/K smem tiles (pad 4 -> conflict-free frags)
#define VSTR 136   // bf16 row stride for V smem tiles (pad 8)
#define NTHREADS 128

// Scratch: Qext (= Kext) [N, 128] fp32 values pre-truncated to tf32.
__device__ float g_qext[NTOK * DE];

__global__ void build_qext_kernel(const float* __restrict__ mag,
                                  const float* __restrict__ phase) {
    int i = blockIdx.x * blockDim.x + threadIdx.x;
    if (i >= NTOK * DHALF) return;
    int row = i >> 6;
    int d = i & 63;
    float m = mag[i];
    float p = phase[i];
    float s, c;
    sincosf(p, &s, &c);
    float a = m * c;
    float b = m * s;
    uint32_t ua, ub;
    asm("cvt.rna.tf32.f32 %0, %1;" : "=r"(ua) : "f"(a));
    asm("cvt.rna.tf32.f32 %0, %1;" : "=r"(ub) : "f"(b));
    g_qext[row * DE + d] = __uint_as_float(ua);
    g_qext[row * DE + DHALF + d] = __uint_as_float(ub);
}

__global__ __launch_bounds__(NTHREADS, 1)
void attn_kernel(const float* __restrict__ mag,
                 const float* __restrict__ phase,
                 float* __restrict__ out) {
    extern __shared__ char smem_raw[];
    float* Qs = (float*)smem_raw;                       // [BM][QSTR]
    float* Ks = Qs + BM * QSTR;                         // [BN][QSTR]
    __nv_bfloat16* Vh = (__nv_bfloat16*)(Ks + BN * QSTR);  // [BN][VSTR]
    __nv_bfloat16* Vl = Vh + BN * VSTR;                    // [BN][VSTR]

    int tid  = threadIdx.x;
    int lane = tid & 31;
    int warp = tid >> 5;
    int q0   = blockIdx.x * BM;
    int mrow = warp * 16;          // this warp's 16 query rows within the block

    int qr = lane >> 2;            // groupID 0..7
    int qc = lane & 3;             // thread-in-group 0..3

    // Load Q tile once (tf32 values from scratch)
    for (int idx = tid * 4; idx < BM * DE; idx += NTHREADS * 4) {
        int r = idx >> 7, c = idx & 127;
        float4 v = *(const float4*)(g_qext + (q0 + r) * DE + c);
        float* dst = Qs + r * QSTR + c;
        dst[0] = v.x; dst[1] = v.y; dst[2] = v.z; dst[3] = v.w;
    }

    // O accumulators: 16 n-tiles of m16n8 covering DE=128 output cols
    float o[16][4];
#pragma unroll
    for (int i = 0; i < 16; i++)
#pragma unroll
        for (int j = 0; j < 4; j++) o[i][j] = 0.f;

    float m0 = -1e30f, m1 = -1e30f;   // running row max (row qr, row qr+8)
    float l0 = 0.f,    l1 = 0.f;      // running row sum (post-bf16-rounding)

    for (int kb = 0; kb < NTOK / BN; kb++) {
        int k0 = kb * BN;
        __syncthreads();   // previous tile fully consumed before overwrite

        // --- Load K tile (tf32) ---
        for (int idx = tid * 4; idx < BN * DE; idx += NTHREADS * 4) {
            int r = idx >> 7, c = idx & 127;
            float4 v = *(const float4*)(g_qext + (k0 + r) * DE + c);
            float* dst = Ks + r * QSTR + c;
            dst[0] = v.x; dst[1] = v.y; dst[2] = v.z; dst[3] = v.w;
        }
        // --- Load V tile = [mag | phase], split into bf16 hi + lo ---
        for (int idx = tid; idx < BN * DHALF; idx += NTHREADS) {
            int r = idx >> 6, c = idx & 63;
            float vm = mag[(k0 + r) * DHALF + c];
            float vp = phase[(k0 + r) * DHALF + c];
            __nv_bfloat16 h = __float2bfloat16(vm);
            __nv_bfloat16 l = __float2bfloat16(vm - __bfloat162float(h));
            Vh[r * VSTR + c] = h;
            Vl[r * VSTR + c] = l;
            h = __float2bfloat16(vp);
            l = __float2bfloat16(vp - __bfloat162float(h));
            Vh[r * VSTR + DHALF + c] = h;
            Vl[r * VSTR + DHALF + c] = l;
        }
        __syncthreads();

        // --- S = Q K^T  (tf32 mma, fp32 accum) ---
        float s[8][4];
#pragma unroll
        for (int i = 0; i < 8; i++) { s[i][0]=0.f; s[i][1]=0.f; s[i][2]=0.f; s[i][3]=0.f; }

#pragma unroll
        for (int kk = 0; kk < DE; kk += 8) {
            uint32_t a0 = __float_as_uint(Qs[(mrow + qr    ) * QSTR + kk + qc    ]);
            uint32_t a1 = __float_as_uint(Qs[(mrow + qr + 8) * QSTR + kk + qc    ]);
            uint32_t a2 = __float_as_uint(Qs[(mrow + qr    ) * QSTR + kk + qc + 4]);
            uint32_t a3 = __float_as_uint(Qs[(mrow + qr + 8) * QSTR + kk + qc + 4]);
#pragma unroll
            for (int nt = 0; nt < 8; nt++) {
                uint32_t b0 = __float_as_uint(Ks[(nt * 8 + qr) * QSTR + kk + qc    ]);
                uint32_t b1 = __float_as_uint(Ks[(nt * 8 + qr) * QSTR + kk + qc + 4]);
                asm volatile(
                    "mma.sync.aligned.m16n8k8.row.col.f32.tf32.tf32.f32 "
                    "{%0,%1,%2,%3}, {%4,%5,%6,%7}, {%8,%9}, {%0,%1,%2,%3};"
                    : "+f"(s[nt][0]), "+f"(s[nt][1]), "+f"(s[nt][2]), "+f"(s[nt][3])
                    : "r"(a0), "r"(a1), "r"(a2), "r"(a3), "r"(b0), "r"(b1));
            }
        }

        // --- Online softmax (rows qr and qr+8) ---
        float mx0 = s[0][0], mx1 = s[0][2];
#pragma unroll
        for (int nt = 0; nt < 8; nt++) {
            mx0 = fmaxf(mx0, fmaxf(s[nt][0], s[nt][1]));
            mx1 = fmaxf(mx1, fmaxf(s[nt][2], s[nt][3]));
        }
        mx0 = fmaxf(mx0, __shfl_xor_sync(0xffffffffu, mx0, 1));
        mx0 = fmaxf(mx0, __shfl_xor_sync(0xffffffffu, mx0, 2));
        mx1 = fmaxf(mx1, __shfl_xor_sync(0xffffffffu, mx1, 1));
        mx1 = fmaxf(mx1, __shfl_xor_sync(0xffffffffu, mx1, 2));

        float mn0 = fmaxf(m0, mx0), mn1 = fmaxf(m1, mx1);
        float corr0 = __expf(m0 - mn0), corr1 = __expf(m1 - mn1);
        m0 = mn0; m1 = mn1;

        uint32_t pa[8][2];
        float sum0 = 0.f, sum1 = 0.f;
#pragma unroll
        for (int nt = 0; nt < 8; nt++) {
            float p0 = __expf(s[nt][0] - mn0);
            float p1 = __expf(s[nt][1] - mn0);
            float p2 = __expf(s[nt][2] - mn1);
            float p3 = __expf(s[nt][3] - mn1);
            __nv_bfloat162 h01; h01.x = __float2bfloat16(p0); h01.y = __float2bfloat16(p1);
            __nv_bfloat162 h23; h23.x = __float2bfloat16(p2); h23.y = __float2bfloat16(p3);
            pa[nt][0] = *(uint32_t*)&h01;
            pa[nt][1] = *(uint32_t*)&h23;
            // sum AFTER rounding so P-rounding cancels between numerator and l
            sum0 += __bfloat162float(h01.x) + __bfloat162float(h01.y);
            sum1 += __bfloat162float(h23.x) + __bfloat162float(h23.y);
        }
        sum0 += __shfl_xor_sync(0xffffffffu, sum0, 1);
        sum0 += __shfl_xor_sync(0xffffffffu, sum0, 2);
        sum1 += __shfl_xor_sync(0xffffffffu, sum1, 1);
        sum1 += __shfl_xor_sync(0xffffffffu, sum1, 2);
        l0 = l0 * corr0 + sum0;
        l1 = l1 * corr1 + sum1;

#pragma unroll
        for (int nt = 0; nt < 16; nt++) {
            o[nt][0] *= corr0; o[nt][1] *= corr0;
            o[nt][2] *= corr1; o[nt][3] *= corr1;
        }

        // --- O += P @ (Vh + Vl)  (bf16 mma, fp32 accum) ---
        int lr = lane & 15;
        int lc = (lane >> 4) << 3;
#pragma unroll
        for (int kt = 0; kt < 4; kt++) {
            uint32_t A0 = pa[2 * kt][0],     A1 = pa[2 * kt][1];
            uint32_t A2 = pa[2 * kt + 1][0], A3 = pa[2 * kt + 1][1];
#pragma unroll
            for (int np = 0; np < 8; np++) {
                const __nv_bfloat16* ph = Vh + (kt * 16 + lr) * VSTR + np * 16 + lc;
                const __nv_bfloat16* pl = Vl + (kt * 16 + lr) * VSTR + np * 16 + lc;
                uint32_t ah = (uint32_t)__cvta_generic_to_shared(ph);
                uint32_t al = (uint32_t)__cvta_generic_to_shared(pl);
                uint32_t b0, b1, b2, b3;
                asm volatile("ldmatrix.sync.aligned.m8n8.x4.trans.shared.b16 "
                             "{%0,%1,%2,%3}, [%4];"
                             : "=r"(b0), "=r"(b1), "=r"(b2), "=r"(b3) : "r"(ah));
                asm volatile(
                    "mma.sync.aligned.m16n8k16.row.col.f32.bf16.bf16.f32 "
                    "{%0,%1,%2,%3}, {%4,%5,%6,%7}, {%8,%9}, {%0,%1,%2,%3};"
                    : "+f"(o[2*np][0]), "+f"(o[2*np][1]), "+f"(o[2*np][2]), "+f"(o[2*np][3])
                    : "r"(A0), "r"(A1), "r"(A2), "r"(A3), "r"(b0), "r"(b1));
                asm volatile(
                    "mma.sync.aligned.m16n8k16.row.col.f32.bf16.bf16.f32 "
                    "{%0,%1,%2,%3}, {%4,%5,%6,%7}, {%8,%9}, {%0,%1,%2,%3};"
                    : "+f"(o[2*np+1][0]), "+f"(o[2*np+1][1]), "+f"(o[2*np+1][2]), "+f"(o[2*np+1][3])
                    : "r"(A0), "r"(A1), "r"(A2), "r"(A3), "r"(b2), "r"(b3));
                asm volatile("ldmatrix.sync.aligned.m8n8.x4.trans.shared.b16 "
                             "{%0,%1,%2,%3}, [%4];"
                             : "=r"(b0), "=r"(b1), "=r"(b2), "=r"(b3) : "r"(al));
                asm volatile(
                    "mma.sync.aligned.m16n8k16.row.col.f32.bf16.bf16.f32 "
                    "{%0,%1,%2,%3}, {%4,%5,%6,%7}, {%8,%9}, {%0,%1,%2,%3};"
                    : "+f"(o[2*np][0]), "+f"(o[2*np][1]), "+f"(o[2*np][2]), "+f"(o[2*np][3])
                    : "r"(A0), "r"(A1), "r"(A2), "r"(A3), "r"(b0), "r"(b1));
                asm volatile(
                    "mma.sync.aligned.m16n8k16.row.col.f32.bf16.bf16.f32 "
                    "{%0,%1,%2,%3}, {%4,%5,%6,%7}, {%8,%9}, {%0,%1,%2,%3};"
                    : "+f"(o[2*np+1][0]), "+f"(o[2*np+1][1]), "+f"(o[2*np+1][2]), "+f"(o[2*np+1][3])
                    : "r"(A0), "r"(A1), "r"(A2), "r"(A3), "r"(b2), "r"(b3));
            }
        }
    }

    // --- Epilogue: normalize, split [mag | phase] halves into d_out ---
    float inv0 = 1.f / l0;
    float inv1 = 1.f / l1;
    int row0 = q0 + mrow + qr;
    int row1 = row0 + 8;
#pragma unroll
    for (int nt = 0; nt < 16; nt++) {
        int col = nt * 8 + 2 * qc;
        float2 v0 = make_float2(o[nt][0] * inv0, o[nt][1] * inv0);
        float2 v1 = make_float2(o[nt][2] * inv1, o[nt][3] * inv1);
        if (col < DHALF) {
            *(float2*)(out + row0 * DHALF + col) = v0;
            *(float2*)(out + row1 * DHALF + col) = v1;
        } else {
            *(float2*)(out + NTOK * DHALF + row0 * DHALF + (col - DHALF)) = v0;
            *(float2*)(out + NTOK * DHALF + row1 * DHALF + (col - DHALF)) = v1;
        }
    }
}

extern "C" void kernel_launch(void* const* d_in, const int* in_sizes, int n_in,
                              void* d_out, int out_size) {
    const float* mag   = (const float*)d_in[0];
    const float* phase = (const float*)d_in[1];
    float* out = (float*)d_out;

    build_qext_kernel<<<(NTOK * DHALF + 255) / 256, 256>>>(mag, phase);

    int smem_bytes = (BM * QSTR + BN * QSTR) * (int)sizeof(float)
                   + 2 * BN * VSTR * (int)sizeof(__nv_bfloat16);   // 102400
    cudaFuncSetAttribute(attn_kernel, cudaFuncAttributeMaxDynamicSharedMemorySize,
                         smem_bytes);
    attn_kernel<<<NTOK / BM, NTHREADS, smem_bytes>>>(mag, phase, out);
}

// round 4
// speedup vs baseline: 1.6164x; 1.6164x over previous
#include <cuda_runtime.h>
#include <cuda_bf16.h>
#include <stdint.h>

#define NTOK 8192
#define DHALF 64
#define DE 128
#define BM 64
#define BN 64
#define QSTR 132   // fp32 row stride for Q/K smem tiles (pad 4 -> conflict-free frags)
#define VSTR 136   // bf16 row stride for V smem tiles (pad 8)
#define NTHREADS 128
#define SPLIT 4
#define TILES_PER_SPLIT (NTOK / BN / SPLIT)   // 32

// Scratch: Qext (= Kext) [N, 128] fp32 values pre-truncated to tf32.
__device__ float g_qext[NTOK * DE];
// Split-K partials: un-normalized O + per-row (m, l) per split.
__device__ float g_part[SPLIT * NTOK * DE];   // 16 MB
__device__ float g_m[SPLIT * NTOK];
__device__ float g_l[SPLIT * NTOK];

__global__ void build_qext_kernel(const float* __restrict__ mag,
                                  const float* __restrict__ phase) {
    int i = blockIdx.x * blockDim.x + threadIdx.x;
    if (i >= NTOK * DHALF) return;
    int row = i >> 6;
    int d = i & 63;
    float m = mag[i];
    float p = phase[i];
    float s, c;
    sincosf(p, &s, &c);
    float a = m * c;
    float b = m * s;
    uint32_t ua, ub;
    asm("cvt.rna.tf32.f32 %0, %1;" : "=r"(ua) : "f"(a));
    asm("cvt.rna.tf32.f32 %0, %1;" : "=r"(ub) : "f"(b));
    g_qext[row * DE + d] = __uint_as_float(ua);
    g_qext[row * DE + DHALF + d] = __uint_as_float(ub);
}

__global__ __launch_bounds__(NTHREADS)
void attn_kernel(const float* __restrict__ mag,
                 const float* __restrict__ phase) {
    extern __shared__ char smem_raw[];
    float* Qs = (float*)smem_raw;                       // [BM][QSTR]
    float* Ks = Qs + BM * QSTR;                         // [BN][QSTR]
    __nv_bfloat16* Vh = (__nv_bfloat16*)(Ks + BN * QSTR);  // [BN][VSTR]
    __nv_bfloat16* Vl = Vh + BN * VSTR;                    // [BN][VSTR]

    int tid  = threadIdx.x;
    int lane = tid & 31;
    int warp = tid >> 5;
    int q0   = blockIdx.x * BM;
    int sp   = blockIdx.y;          // kv split index
    int mrow = warp * 16;           // this warp's 16 query rows within the block

    int qr = lane >> 2;             // groupID 0..7
    int qc = lane & 3;              // thread-in-group 0..3

    // Load Q tile once (tf32 values from scratch)
    for (int idx = tid * 4; idx < BM * DE; idx += NTHREADS * 4) {
        int r = idx >> 7, c = idx & 127;
        float4 v = *(const float4*)(g_qext + (q0 + r) * DE + c);
        float* dst = Qs + r * QSTR + c;
        dst[0] = v.x; dst[1] = v.y; dst[2] = v.z; dst[3] = v.w;
    }

    // O accumulators: 16 n-tiles of m16n8 covering DE=128 output cols
    float o[16][4];
#pragma unroll
    for (int i = 0; i < 16; i++)
#pragma unroll
        for (int j = 0; j < 4; j++) o[i][j] = 0.f;

    float m0 = -1e30f, m1 = -1e30f;   // running row max (row qr, row qr+8)
    float l0 = 0.f,    l1 = 0.f;      // running row sum (post-bf16-rounding)

    int kb_begin = sp * TILES_PER_SPLIT;
    int kb_end   = kb_begin + TILES_PER_SPLIT;
    for (int kb = kb_begin; kb < kb_end; kb++) {
        int k0 = kb * BN;
        __syncthreads();   // previous tile fully consumed before overwrite

        // --- Load K tile (tf32) ---
        for (int idx = tid * 4; idx < BN * DE; idx += NTHREADS * 4) {
            int r = idx >> 7, c = idx & 127;
            float4 v = *(const float4*)(g_qext + (k0 + r) * DE + c);
            float* dst = Ks + r * QSTR + c;
            dst[0] = v.x; dst[1] = v.y; dst[2] = v.z; dst[3] = v.w;
        }
        // --- Load V tile = [mag | phase], split into bf16 hi + lo ---
        for (int idx = tid; idx < BN * DHALF; idx += NTHREADS) {
            int r = idx >> 6, c = idx & 63;
            float vm = mag[(k0 + r) * DHALF + c];
            float vp = phase[(k0 + r) * DHALF + c];
            __nv_bfloat16 h = __float2bfloat16(vm);
            __nv_bfloat16 l = __float2bfloat16(vm - __bfloat162float(h));
            Vh[r * VSTR + c] = h;
            Vl[r * VSTR + c] = l;
            h = __float2bfloat16(vp);
            l = __float2bfloat16(vp - __bfloat162float(h));
            Vh[r * VSTR + DHALF + c] = h;
            Vl[r * VSTR + DHALF + c] = l;
        }
        __syncthreads();

        // --- S = Q K^T  (tf32 mma, fp32 accum) ---
        float s[8][4];
#pragma unroll
        for (int i = 0; i < 8; i++) { s[i][0]=0.f; s[i][1]=0.f; s[i][2]=0.f; s[i][3]=0.f; }

#pragma unroll
        for (int kk = 0; kk < DE; kk += 8) {
            uint32_t a0 = __float_as_uint(Qs[(mrow + qr    ) * QSTR + kk + qc    ]);
            uint32_t a1 = __float_as_uint(Qs[(mrow + qr + 8) * QSTR + kk + qc    ]);
            uint32_t a2 = __float_as_uint(Qs[(mrow + qr    ) * QSTR + kk + qc + 4]);
            uint32_t a3 = __float_as_uint(Qs[(mrow + qr + 8) * QSTR + kk + qc + 4]);
#pragma unroll
            for (int nt = 0; nt < 8; nt++) {
                uint32_t b0 = __float_as_uint(Ks[(nt * 8 + qr) * QSTR + kk + qc    ]);
                uint32_t b1 = __float_as_uint(Ks[(nt * 8 + qr) * QSTR + kk + qc + 4]);
                asm volatile(
                    "mma.sync.aligned.m16n8k8.row.col.f32.tf32.tf32.f32 "
                    "{%0,%1,%2,%3}, {%4,%5,%6,%7}, {%8,%9}, {%0,%1,%2,%3};"
                    : "+f"(s[nt][0]), "+f"(s[nt][1]), "+f"(s[nt][2]), "+f"(s[nt][3])
                    : "r"(a0), "r"(a1), "r"(a2), "r"(a3), "r"(b0), "r"(b1));
            }
        }

        // --- Online softmax (rows qr and qr+8) ---
        float mx0 = s[0][0], mx1 = s[0][2];
#pragma unroll
        for (int nt = 0; nt < 8; nt++) {
            mx0 = fmaxf(mx0, fmaxf(s[nt][0], s[nt][1]));
            mx1 = fmaxf(mx1, fmaxf(s[nt][2], s[nt][3]));
        }
        mx0 = fmaxf(mx0, __shfl_xor_sync(0xffffffffu, mx0, 1));
        mx0 = fmaxf(mx0, __shfl_xor_sync(0xffffffffu, mx0, 2));
        mx1 = fmaxf(mx1, __shfl_xor_sync(0xffffffffu, mx1, 1));
        mx1 = fmaxf(mx1, __shfl_xor_sync(0xffffffffu, mx1, 2));

        float mn0 = fmaxf(m0, mx0), mn1 = fmaxf(m1, mx1);
        float corr0 = __expf(m0 - mn0), corr1 = __expf(m1 - mn1);
        m0 = mn0; m1 = mn1;

        uint32_t pa[8][2];
        float sum0 = 0.f, sum1 = 0.f;
#pragma unroll
        for (int nt = 0; nt < 8; nt++) {
            float p0 = __expf(s[nt][0] - mn0);
            float p1 = __expf(s[nt][1] - mn0);
            float p2 = __expf(s[nt][2] - mn1);
            float p3 = __expf(s[nt][3] - mn1);
            __nv_bfloat162 h01; h01.x = __float2bfloat16(p0); h01.y = __float2bfloat16(p1);
            __nv_bfloat162 h23; h23.x = __float2bfloat16(p2); h23.y = __float2bfloat16(p3);
            pa[nt][0] = *(uint32_t*)&h01;
            pa[nt][1] = *(uint32_t*)&h23;
            // sum AFTER rounding so P-rounding cancels between numerator and l
            sum0 += __bfloat162float(h01.x) + __bfloat162float(h01.y);
            sum1 += __bfloat162float(h23.x) + __bfloat162float(h23.y);
        }
        sum0 += __shfl_xor_sync(0xffffffffu, sum0, 1);
        sum0 += __shfl_xor_sync(0xffffffffu, sum0, 2);
        sum1 += __shfl_xor_sync(0xffffffffu, sum1, 1);
        sum1 += __shfl_xor_sync(0xffffffffu, sum1, 2);
        l0 = l0 * corr0 + sum0;
        l1 = l1 * corr1 + sum1;

#pragma unroll
        for (int nt = 0; nt < 16; nt++) {
            o[nt][0] *= corr0; o[nt][1] *= corr0;
            o[nt][2] *= corr1; o[nt][3] *= corr1;
        }

        // --- O += P @ (Vh + Vl)  (bf16 mma, fp32 accum) ---
        int lr = lane & 15;
        int lc = (lane >> 4) << 3;
#pragma unroll
        for (int kt = 0; kt < 4; kt++) {
            uint32_t A0 = pa[2 * kt][0],     A1 = pa[2 * kt][1];
            uint32_t A2 = pa[2 * kt + 1][0], A3 = pa[2 * kt + 1][1];
#pragma unroll
            for (int np = 0; np < 8; np++) {
                const __nv_bfloat16* ph = Vh + (kt * 16 + lr) * VSTR + np * 16 + lc;
                const __nv_bfloat16* pl = Vl + (kt * 16 + lr) * VSTR + np * 16 + lc;
                uint32_t ah = (uint32_t)__cvta_generic_to_shared(ph);
                uint32_t al = (uint32_t)__cvta_generic_to_shared(pl);
                uint32_t b0, b1, b2, b3;
                asm volatile("ldmatrix.sync.aligned.m8n8.x4.trans.shared.b16 "
                             "{%0,%1,%2,%3}, [%4];"
                             : "=r"(b0), "=r"(b1), "=r"(b2), "=r"(b3) : "r"(ah));
                asm volatile(
                    "mma.sync.aligned.m16n8k16.row.col.f32.bf16.bf16.f32 "
                    "{%0,%1,%2,%3}, {%4,%5,%6,%7}, {%8,%9}, {%0,%1,%2,%3};"
                    : "+f"(o[2*np][0]), "+f"(o[2*np][1]), "+f"(o[2*np][2]), "+f"(o[2*np][3])
                    : "r"(A0), "r"(A1), "r"(A2), "r"(A3), "r"(b0), "r"(b1));
                asm volatile(
                    "mma.sync.aligned.m16n8k16.row.col.f32.bf16.bf16.f32 "
                    "{%0,%1,%2,%3}, {%4,%5,%6,%7}, {%8,%9}, {%0,%1,%2,%3};"
                    : "+f"(o[2*np+1][0]), "+f"(o[2*np+1][1]), "+f"(o[2*np+1][2]), "+f"(o[2*np+1][3])
                    : "r"(A0), "r"(A1), "r"(A2), "r"(A3), "r"(b2), "r"(b3));
                asm volatile("ldmatrix.sync.aligned.m8n8.x4.trans.shared.b16 "
                             "{%0,%1,%2,%3}, [%4];"
                             : "=r"(b0), "=r"(b1), "=r"(b2), "=r"(b3) : "r"(al));
                asm volatile(
                    "mma.sync.aligned.m16n8k16.row.col.f32.bf16.bf16.f32 "
                    "{%0,%1,%2,%3}, {%4,%5,%6,%7}, {%8,%9}, {%0,%1,%2,%3};"
                    : "+f"(o[2*np][0]), "+f"(o[2*np][1]), "+f"(o[2*np][2]), "+f"(o[2*np][3])
                    : "r"(A0), "r"(A1), "r"(A2), "r"(A3), "r"(b0), "r"(b1));
                asm volatile(
                    "mma.sync.aligned.m16n8k16.row.col.f32.bf16.bf16.f32 "
                    "{%0,%1,%2,%3}, {%4,%5,%6,%7}, {%8,%9}, {%0,%1,%2,%3};"
                    : "+f"(o[2*np+1][0]), "+f"(o[2*np+1][1]), "+f"(o[2*np+1][2]), "+f"(o[2*np+1][3])
                    : "r"(A0), "r"(A1), "r"(A2), "r"(A3), "r"(b2), "r"(b3));
            }
        }
    }

    // --- Epilogue: store un-normalized partial O + (m, l) for this split ---
    int row0 = q0 + mrow + qr;
    int row1 = row0 + 8;
    float* part = g_part + sp * (NTOK * DE);
#pragma unroll
    for (int nt = 0; nt < 16; nt++) {
        int col = nt * 8 + 2 * qc;
        *(float2*)(part + row0 * DE + col) = make_float2(o[nt][0], o[nt][1]);
        *(float2*)(part + row1 * DE + col) = make_float2(o[nt][2], o[nt][3]);
    }
    if (qc == 0) {
        g_m[sp * NTOK + row0] = m0;
        g_l[sp * NTOK + row0] = l0;
        g_m[sp * NTOK + row1] = m1;
        g_l[sp * NTOK + row1] = l1;
    }
}

// Merge SPLIT partials per row: out = sum_s(O_s * e^{m_s-M}) / sum_s(l_s * e^{m_s-M})
__global__ void combine_kernel(float* __restrict__ out) {
    int idx = blockIdx.x * blockDim.x + threadIdx.x;   // row * DE + col
    if (idx >= NTOK * DE) return;
    int row = idx >> 7;
    int col = idx & 127;

    float M = -1e30f;
#pragma unroll
    for (int s = 0; s < SPLIT; s++) M = fmaxf(M, g_m[s * NTOK + row]);
    float L = 0.f, acc = 0.f;
#pragma unroll
    for (int s = 0; s < SPLIT; s++) {
        float w = __expf(g_m[s * NTOK + row] - M);
        L   += g_l[s * NTOK + row] * w;
        acc += g_part[s * (NTOK * DE) + row * DE + col] * w;
    }
    float r = acc / L;
    if (col < DHALF) out[row * DHALF + col] = r;
    else             out[NTOK * DHALF + row * DHALF + (col - DHALF)] = r;
}

extern "C" void kernel_launch(void* const* d_in, const int* in_sizes, int n_in,
                              void* d_out, int out_size) {
    const float* mag   = (const float*)d_in[0];
    const float* phase = (const float*)d_in[1];
    float* out = (float*)d_out;

    build_qext_kernel<<<(NTOK * DHALF + 255) / 256, 256>>>(mag, phase);

    int smem_bytes = (BM * QSTR + BN * QSTR) * (int)sizeof(float)
                   + 2 * BN * VSTR * (int)sizeof(__nv_bfloat16);   // 102400
    cudaFuncSetAttribute(attn_kernel, cudaFuncAttributeMaxDynamicSharedMemorySize,
                         smem_bytes);
    dim3 grid(NTOK / BM, SPLIT);
    attn_kernel<<<grid, NTHREADS, smem_bytes>>>(mag, phase);

    combine_kernel<<<(NTOK * DE + 255) / 256, 256>>>(out);
}

// round 5
// speedup vs baseline: 1.6733x; 1.0352x over previous
#include <cuda_runtime.h>
#include <cuda_bf16.h>
#include <stdint.h>

#define NTOK 8192
#define DHALF 64
#define DE 128
#define BM 64
#define BN 32
#define QSTR 132   // fp32 row stride for Q/K smem tiles (pad 4 -> conflict-free frags)
#define VSTR 136   // bf16 row stride for V smem tiles (pad 8)
#define NTHREADS 128
#define SPLIT 4
#define TILES_PER_SPLIT (NTOK / BN / SPLIT)   // 64

// Scratch: Qext (= Kext) [N, 128] fp32 values pre-truncated to tf32.
__device__ float g_qext[NTOK * DE];
// Precomputed V = [mag | phase] split into bf16 hi + lo. [N, 128] each.
__device__ __nv_bfloat16 g_vh[NTOK * DE];
__device__ __nv_bfloat16 g_vl[NTOK * DE];
// Split-K partials: un-normalized O + per-row (m, l) per split.
__device__ float g_part[SPLIT * NTOK * DE];   // 16 MB
__device__ float g_m[SPLIT * NTOK];
__device__ float g_l[SPLIT * NTOK];

#define CP_ASYNC16(dst_u32, src_ptr) \
    asm volatile("cp.async.cg.shared.global [%0], [%1], 16;" \
                 :: "r"(dst_u32), "l"(src_ptr))
#define CP_COMMIT()  asm volatile("cp.async.commit_group;")
#define CP_WAIT1()   asm volatile("cp.async.wait_group 1;")

__global__ void build_qext_kernel(const float* __restrict__ mag,
                                  const float* __restrict__ phase) {
    int i = blockIdx.x * blockDim.x + threadIdx.x;
    if (i >= NTOK * DHALF) return;
    int row = i >> 6;
    int d = i & 63;
    float m = mag[i];
    float p = phase[i];
    float s, c;
    sincosf(p, &s, &c);
    float a = m * c;
    float b = m * s;
    uint32_t ua, ub;
    asm("cvt.rna.tf32.f32 %0, %1;" : "=r"(ua) : "f"(a));
    asm("cvt.rna.tf32.f32 %0, %1;" : "=r"(ub) : "f"(b));
    g_qext[row * DE + d] = __uint_as_float(ua);
    g_qext[row * DE + DHALF + d] = __uint_as_float(ub);

    // V hi/lo split (identical math to the old in-loop transform)
    __nv_bfloat16 h = __float2bfloat16(m);
    __nv_bfloat16 l = __float2bfloat16(m - __bfloat162float(h));
    g_vh[row * DE + d] = h;
    g_vl[row * DE + d] = l;
    h = __float2bfloat16(p);
    l = __float2bfloat16(p - __bfloat162float(h));
    g_vh[row * DE + DHALF + d] = h;
    g_vl[row * DE + DHALF + d] = l;
}

__global__ __launch_bounds__(NTHREADS)
void attn_kernel() {
    extern __shared__ char smem_raw[];
    float* Qs = (float*)smem_raw;                           // [BM][QSTR]
    float* Ks = Qs + BM * QSTR;                             // [2][BN][QSTR]
    __nv_bfloat16* Vh = (__nv_bfloat16*)(Ks + 2 * BN * QSTR); // [2][BN][VSTR]
    __nv_bfloat16* Vl = Vh + 2 * BN * VSTR;                   // [2][BN][VSTR]

    int tid  = threadIdx.x;
    int lane = tid & 31;
    int warp = tid >> 5;
    int q0   = blockIdx.x * BM;
    int sp   = blockIdx.y;          // kv split index
    int mrow = warp * 16;           // this warp's 16 query rows within the block

    int qr = lane >> 2;             // groupID 0..7
    int qc = lane & 3;              // thread-in-group 0..3

    int kb_begin = sp * TILES_PER_SPLIT;

    // --- async-copy issue for one KV tile into buffer `buf` ---
    auto issue_tile = [&](int buf, int kb) {
        int k0 = kb * BN;
        float* kdst_base = Ks + buf * BN * QSTR;
        __nv_bfloat16* vhdst_base = Vh + buf * BN * VSTR;
        __nv_bfloat16* vldst_base = Vl + buf * BN * VSTR;
        // K: 32 rows x 128 fp32 = 32 chunks(16B)/row -> 1024 chunks
#pragma unroll
        for (int it = 0; it < 8; it++) {
            int idx = tid + it * NTHREADS;
            int r = idx >> 5, c = idx & 31;             // chunk col (x4 floats)
            uint32_t dst = (uint32_t)__cvta_generic_to_shared(
                kdst_base + r * QSTR + c * 4);
            CP_ASYNC16(dst, g_qext + (k0 + r) * DE + c * 4);
        }
        // Vh / Vl: 32 rows x 128 bf16 = 16 chunks/row -> 512 chunks each
#pragma unroll
        for (int it = 0; it < 4; it++) {
            int idx = tid + it * NTHREADS;
            int r = idx >> 4, c = idx & 15;             // chunk col (x8 bf16)
            uint32_t dh = (uint32_t)__cvta_generic_to_shared(
                vhdst_base + r * VSTR + c * 8);
            uint32_t dl = (uint32_t)__cvta_generic_to_shared(
                vldst_base + r * VSTR + c * 8);
            CP_ASYNC16(dh, g_vh + (k0 + r) * DE + c * 8);
            CP_ASYNC16(dl, g_vl + (k0 + r) * DE + c * 8);
        }
        CP_COMMIT();
    };

    // Load Q tile once (tf32 values from scratch)
    for (int idx = tid * 4; idx < BM * DE; idx += NTHREADS * 4) {
        int r = idx >> 7, c = idx & 127;
        float4 v = *(const float4*)(g_qext + (q0 + r) * DE + c);
        float* dst = Qs + r * QSTR + c;
        dst[0] = v.x; dst[1] = v.y; dst[2] = v.z; dst[3] = v.w;
    }

    // Prologue: fill both pipeline stages
    issue_tile(0, kb_begin);
    issue_tile(1, kb_begin + 1);

    // O accumulators: 16 n-tiles of m16n8 covering DE=128 output cols
    float o[16][4];
#pragma unroll
    for (int i = 0; i < 16; i++)
#pragma unroll
        for (int j = 0; j < 4; j++) o[i][j] = 0.f;

    float m0 = -1e30f, m1 = -1e30f;   // running row max (row qr, row qr+8)
    float l0 = 0.f,    l1 = 0.f;      // running row sum (post-bf16-rounding)

    for (int i = 0; i < TILES_PER_SPLIT; i++) {
        int buf = i & 1;
        float* Kb = Ks + buf * BN * QSTR;
        __nv_bfloat16* Vhb = Vh + buf * BN * VSTR;
        __nv_bfloat16* Vlb = Vl + buf * BN * VSTR;

        CP_WAIT1();        // oldest group (this buf) complete
        __syncthreads();   // visibility across warps

        // --- S = Q K^T  (tf32 mma, fp32 accum), BN=32 -> 4 n-tiles ---
        float s[4][4];
#pragma unroll
        for (int t = 0; t < 4; t++) { s[t][0]=0.f; s[t][1]=0.f; s[t][2]=0.f; s[t][3]=0.f; }

#pragma unroll
        for (int kk = 0; kk < DE; kk += 8) {
            uint32_t a0 = __float_as_uint(Qs[(mrow + qr    ) * QSTR + kk + qc    ]);
            uint32_t a1 = __float_as_uint(Qs[(mrow + qr + 8) * QSTR + kk + qc    ]);
            uint32_t a2 = __float_as_uint(Qs[(mrow + qr    ) * QSTR + kk + qc + 4]);
            uint32_t a3 = __float_as_uint(Qs[(mrow + qr + 8) * QSTR + kk + qc + 4]);
#pragma unroll
            for (int nt = 0; nt < 4; nt++) {
                uint32_t b0 = __float_as_uint(Kb[(nt * 8 + qr) * QSTR + kk + qc    ]);
                uint32_t b1 = __float_as_uint(Kb[(nt * 8 + qr) * QSTR + kk + qc + 4]);
                asm volatile(
                    "mma.sync.aligned.m16n8k8.row.col.f32.tf32.tf32.f32 "
                    "{%0,%1,%2,%3}, {%4,%5,%6,%7}, {%8,%9}, {%0,%1,%2,%3};"
                    : "+f"(s[nt][0]), "+f"(s[nt][1]), "+f"(s[nt][2]), "+f"(s[nt][3])
                    : "r"(a0), "r"(a1), "r"(a2), "r"(a3), "r"(b0), "r"(b1));
            }
        }

        // --- Online softmax (rows qr and qr+8) ---
        float mx0 = s[0][0], mx1 = s[0][2];
#pragma unroll
        for (int nt = 0; nt < 4; nt++) {
            mx0 = fmaxf(mx0, fmaxf(s[nt][0], s[nt][1]));
            mx1 = fmaxf(mx1, fmaxf(s[nt][2], s[nt][3]));
        }
        mx0 = fmaxf(mx0, __shfl_xor_sync(0xffffffffu, mx0, 1));
        mx0 = fmaxf(mx0, __shfl_xor_sync(0xffffffffu, mx0, 2));
        mx1 = fmaxf(mx1, __shfl_xor_sync(0xffffffffu, mx1, 1));
        mx1 = fmaxf(mx1, __shfl_xor_sync(0xffffffffu, mx1, 2));

        float mn0 = fmaxf(m0, mx0), mn1 = fmaxf(m1, mx1);
        float corr0 = __expf(m0 - mn0), corr1 = __expf(m1 - mn1);
        m0 = mn0; m1 = mn1;

        uint32_t pa[4][2];
        float sum0 = 0.f, sum1 = 0.f;
#pragma unroll
        for (int nt = 0; nt < 4; nt++) {
            float p0 = __expf(s[nt][0] - mn0);
            float p1 = __expf(s[nt][1] - mn0);
            float p2 = __expf(s[nt][2] - mn1);
            float p3 = __expf(s[nt][3] - mn1);
            __nv_bfloat162 h01; h01.x = __float2bfloat16(p0); h01.y = __float2bfloat16(p1);
            __nv_bfloat162 h23; h23.x = __float2bfloat16(p2); h23.y = __float2bfloat16(p3);
            pa[nt][0] = *(uint32_t*)&h01;
            pa[nt][1] = *(uint32_t*)&h23;
            // sum AFTER rounding so P-rounding cancels between numerator and l
            sum0 += __bfloat162float(h01.x) + __bfloat162float(h01.y);
            sum1 += __bfloat162float(h23.x) + __bfloat162float(h23.y);
        }
        sum0 += __shfl_xor_sync(0xffffffffu, sum0, 1);
        sum0 += __shfl_xor_sync(0xffffffffu, sum0, 2);
        sum1 += __shfl_xor_sync(0xffffffffu, sum1, 1);
        sum1 += __shfl_xor_sync(0xffffffffu, sum1, 2);
        l0 = l0 * corr0 + sum0;
        l1 = l1 * corr1 + sum1;

#pragma unroll
        for (int nt = 0; nt < 16; nt++) {
            o[nt][0] *= corr0; o[nt][1] *= corr0;
            o[nt][2] *= corr1; o[nt][3] *= corr1;
        }

        // --- O += P @ (Vh + Vl)  (bf16 mma, fp32 accum), BN=32 -> 2 k-tiles ---
        int lr = lane & 15;
        int lc = (lane >> 4) << 3;
#pragma unroll
        for (int kt = 0; kt < 2; kt++) {
            uint32_t A0 = pa[2 * kt][0],     A1 = pa[2 * kt][1];
            uint32_t A2 = pa[2 * kt + 1][0], A3 = pa[2 * kt + 1][1];
#pragma unroll
            for (int np = 0; np < 8; np++) {
                const __nv_bfloat16* ph = Vhb + (kt * 16 + lr) * VSTR + np * 16 + lc;
                const __nv_bfloat16* pl = Vlb + (kt * 16 + lr) * VSTR + np * 16 + lc;
                uint32_t ah = (uint32_t)__cvta_generic_to_shared(ph);
                uint32_t al = (uint32_t)__cvta_generic_to_shared(pl);
                uint32_t b0, b1, b2, b3;
                asm volatile("ldmatrix.sync.aligned.m8n8.x4.trans.shared.b16 "
                             "{%0,%1,%2,%3}, [%4];"
                             : "=r"(b0), "=r"(b1), "=r"(b2), "=r"(b3) : "r"(ah));
                asm volatile(
                    "mma.sync.aligned.m16n8k16.row.col.f32.bf16.bf16.f32 "
                    "{%0,%1,%2,%3}, {%4,%5,%6,%7}, {%8,%9}, {%0,%1,%2,%3};"
                    : "+f"(o[2*np][0]), "+f"(o[2*np][1]), "+f"(o[2*np][2]), "+f"(o[2*np][3])
                    : "r"(A0), "r"(A1), "r"(A2), "r"(A3), "r"(b0), "r"(b1));
                asm volatile(
                    "mma.sync.aligned.m16n8k16.row.col.f32.bf16.bf16.f32 "
                    "{%0,%1,%2,%3}, {%4,%5,%6,%7}, {%8,%9}, {%0,%1,%2,%3};"
                    : "+f"(o[2*np+1][0]), "+f"(o[2*np+1][1]), "+f"(o[2*np+1][2]), "+f"(o[2*np+1][3])
                    : "r"(A0), "r"(A1), "r"(A2), "r"(A3), "r"(b2), "r"(b3));
                asm volatile("ldmatrix.sync.aligned.m8n8.x4.trans.shared.b16 "
                             "{%0,%1,%2,%3}, [%4];"
                             : "=r"(b0), "=r"(b1), "=r"(b2), "=r"(b3) : "r"(al));
                asm volatile(
                    "mma.sync.aligned.m16n8k16.row.col.f32.bf16.bf16.f32 "
                    "{%0,%1,%2,%3}, {%4,%5,%6,%7}, {%8,%9}, {%0,%1,%2,%3};"
                    : "+f"(o[2*np][0]), "+f"(o[2*np][1]), "+f"(o[2*np][2]), "+f"(o[2*np][3])
                    : "r"(A0), "r"(A1), "r"(A2), "r"(A3), "r"(b0), "r"(b1));
                asm volatile(
                    "mma.sync.aligned.m16n8k16.row.col.f32.bf16.bf16.f32 "
                    "{%0,%1,%2,%3}, {%4,%5,%6,%7}, {%8,%9}, {%0,%1,%2,%3};"
                    : "+f"(o[2*np+1][0]), "+f"(o[2*np+1][1]), "+f"(o[2*np+1][2]), "+f"(o[2*np+1][3])
                    : "r"(A0), "r"(A1), "r"(A2), "r"(A3), "r"(b2), "r"(b3));
            }
        }

        __syncthreads();   // all warps done with this buf before refill
        if (i + 2 < TILES_PER_SPLIT) issue_tile(buf, kb_begin + i + 2);
        else CP_COMMIT();  // keep group count aligned for wait_group
    }

    // --- Epilogue: store un-normalized partial O + (m, l) for this split ---
    int row0 = q0 + mrow + qr;
    int row1 = row0 + 8;
    float* part = g_part + sp * (NTOK * DE);
#pragma unroll
    for (int nt = 0; nt < 16; nt++) {
        int col = nt * 8 + 2 * qc;
        *(float2*)(part + row0 * DE + col) = make_float2(o[nt][0], o[nt][1]);
        *(float2*)(part + row1 * DE + col) = make_float2(o[nt][2], o[nt][3]);
    }
    if (qc == 0) {
        g_m[sp * NTOK + row0] = m0;
        g_l[sp * NTOK + row0] = l0;
        g_m[sp * NTOK + row1] = m1;
        g_l[sp * NTOK + row1] = l1;
    }
}

// Merge SPLIT partials per row: out = sum_s(O_s * e^{m_s-M}) / sum_s(l_s * e^{m_s-M})
__global__ void combine_kernel(float* __restrict__ out) {
    int idx = blockIdx.x * blockDim.x + threadIdx.x;   // row * DE + col
    if (idx >= NTOK * DE) return;
    int row = idx >> 7;
    int col = idx & 127;

    float M = -1e30f;
#pragma unroll
    for (int s = 0; s < SPLIT; s++) M = fmaxf(M, g_m[s * NTOK + row]);
    float L = 0.f, acc = 0.f;
#pragma unroll
    for (int s = 0; s < SPLIT; s++) {
        float w = __expf(g_m[s * NTOK + row] - M);
        L   += g_l[s * NTOK + row] * w;
        acc += g_part[s * (NTOK * DE) + row * DE + col] * w;
    }
    float r = acc / L;
    if (col < DHALF) out[row * DHALF + col] = r;
    else             out[NTOK * DHALF + row * DHALF + (col - DHALF)] = r;
}

extern "C" void kernel_launch(void* const* d_in, const int* in_sizes, int n_in,
                              void* d_out, int out_size) {
    const float* mag   = (const float*)d_in[0];
    const float* phase = (const float*)d_in[1];
    float* out = (float*)d_out;

    build_qext_kernel<<<(NTOK * DHALF + 255) / 256, 256>>>(mag, phase);

    int smem_bytes = (BM * QSTR + 2 * BN * QSTR) * (int)sizeof(float)
                   + 4 * BN * VSTR * (int)sizeof(__nv_bfloat16);   // 102400
    cudaFuncSetAttribute(attn_kernel, cudaFuncAttributeMaxDynamicSharedMemorySize,
                         smem_bytes);
    dim3 grid(NTOK / BM, SPLIT);
    attn_kernel<<<grid, NTHREADS, smem_bytes>>>();

    combine_kernel<<<(NTOK * DE + 255) / 256, 256>>>(out);
}

// round 6
// speedup vs baseline: 1.7545x; 1.0486x over previous
#include <cuda_runtime.h>
#include <cuda_bf16.h>
#include <stdint.h>

#define NTOK 8192
#define DHALF 64
#define DE 128
#define BM 64
#define BN 32
#define QSTR 132   // fp32 row stride for Q/K smem tiles (pad 4 -> conflict-free frags)
#define VSTR 136   // bf16 row stride for V smem tiles (pad 8)
#define NTHREADS 128
#define SPLIT 4
#define TILES_PER_SPLIT (NTOK / BN / SPLIT)   // 64
#define MAXS 64.0f   // provable upper bound on scores: |s_ij| <= D * max(mag)^2 <= 64

// Scratch: Qext (= Kext) [N, 128] fp32 values pre-truncated to tf32.
__device__ float g_qext[NTOK * DE];
// Precomputed V = [mag | phase] split into bf16 hi + lo. [N, 128] each.
__device__ __nv_bfloat16 g_vh[NTOK * DE];
__device__ __nv_bfloat16 g_vl[NTOK * DE];
// Split-K partials: un-normalized O + per-row l per split (fixed-max softmax -> no m).
__device__ float g_part[SPLIT * NTOK * DE];   // 16 MB
__device__ float g_l[SPLIT * NTOK];

#define CP_ASYNC16(dst_u32, src_ptr) \
    asm volatile("cp.async.cg.shared.global [%0], [%1], 16;" \
                 :: "r"(dst_u32), "l"(src_ptr))
#define CP_COMMIT()  asm volatile("cp.async.commit_group;")
#define CP_WAIT1()   asm volatile("cp.async.wait_group 1;")

__global__ void build_qext_kernel(const float* __restrict__ mag,
                                  const float* __restrict__ phase) {
    int i = blockIdx.x * blockDim.x + threadIdx.x;
    if (i >= NTOK * DHALF) return;
    int row = i >> 6;
    int d = i & 63;
    float m = mag[i];
    float p = phase[i];
    float s, c;
    sincosf(p, &s, &c);
    float a = m * c;
    float b = m * s;
    uint32_t ua, ub;
    asm("cvt.rna.tf32.f32 %0, %1;" : "=r"(ua) : "f"(a));
    asm("cvt.rna.tf32.f32 %0, %1;" : "=r"(ub) : "f"(b));
    g_qext[row * DE + d] = __uint_as_float(ua);
    g_qext[row * DE + DHALF + d] = __uint_as_float(ub);

    // V hi/lo split
    __nv_bfloat16 h = __float2bfloat16(m);
    __nv_bfloat16 l = __float2bfloat16(m - __bfloat162float(h));
    g_vh[row * DE + d] = h;
    g_vl[row * DE + d] = l;
    h = __float2bfloat16(p);
    l = __float2bfloat16(p - __bfloat162float(h));
    g_vh[row * DE + DHALF + d] = h;
    g_vl[row * DE + DHALF + d] = l;
}

__global__ __launch_bounds__(NTHREADS)
void attn_kernel() {
    extern __shared__ char smem_raw[];
    float* Qs = (float*)smem_raw;                           // [BM][QSTR]
    float* Ks = Qs + BM * QSTR;                             // [2][BN][QSTR]
    __nv_bfloat16* Vh = (__nv_bfloat16*)(Ks + 2 * BN * QSTR); // [2][BN][VSTR]
    __nv_bfloat16* Vl = Vh + 2 * BN * VSTR;                   // [2][BN][VSTR]

    int tid  = threadIdx.x;
    int lane = tid & 31;
    int warp = tid >> 5;
    int q0   = blockIdx.x * BM;
    int sp   = blockIdx.y;          // kv split index
    int mrow = warp * 16;           // this warp's 16 query rows within the block

    int qr = lane >> 2;             // groupID 0..7
    int qc = lane & 3;              // thread-in-group 0..3

    int kb_begin = sp * TILES_PER_SPLIT;

    // --- async-copy issue for one KV tile into buffer `buf` ---
    auto issue_tile = [&](int buf, int kb) {
        int k0 = kb * BN;
        float* kdst_base = Ks + buf * BN * QSTR;
        __nv_bfloat16* vhdst_base = Vh + buf * BN * VSTR;
        __nv_bfloat16* vldst_base = Vl + buf * BN * VSTR;
#pragma unroll
        for (int it = 0; it < 8; it++) {
            int idx = tid + it * NTHREADS;
            int r = idx >> 5, c = idx & 31;             // chunk col (x4 floats)
            uint32_t dst = (uint32_t)__cvta_generic_to_shared(
                kdst_base + r * QSTR + c * 4);
            CP_ASYNC16(dst, g_qext + (k0 + r) * DE + c * 4);
        }
#pragma unroll
        for (int it = 0; it < 4; it++) {
            int idx = tid + it * NTHREADS;
            int r = idx >> 4, c = idx & 15;             // chunk col (x8 bf16)
            uint32_t dh = (uint32_t)__cvta_generic_to_shared(
                vhdst_base + r * VSTR + c * 8);
            uint32_t dl = (uint32_t)__cvta_generic_to_shared(
                vldst_base + r * VSTR + c * 8);
            CP_ASYNC16(dh, g_vh + (k0 + r) * DE + c * 8);
            CP_ASYNC16(dl, g_vl + (k0 + r) * DE + c * 8);
        }
        CP_COMMIT();
    };

    // Load Q tile once (tf32 values from scratch)
    for (int idx = tid * 4; idx < BM * DE; idx += NTHREADS * 4) {
        int r = idx >> 7, c = idx & 127;
        float4 v = *(const float4*)(g_qext + (q0 + r) * DE + c);
        float* dst = Qs + r * QSTR + c;
        dst[0] = v.x; dst[1] = v.y; dst[2] = v.z; dst[3] = v.w;
    }

    // Prologue: fill both pipeline stages
    issue_tile(0, kb_begin);
    issue_tile(1, kb_begin + 1);

    // O accumulators: 16 n-tiles of m16n8 covering DE=128 output cols
    float o[16][4];
#pragma unroll
    for (int i = 0; i < 16; i++)
#pragma unroll
        for (int j = 0; j < 4; j++) o[i][j] = 0.f;

    float l0 = 0.f, l1 = 0.f;   // thread-local partial row sums (reduced at end)

    for (int i = 0; i < TILES_PER_SPLIT; i++) {
        int buf = i & 1;
        float* Kb = Ks + buf * BN * QSTR;
        __nv_bfloat16* Vhb = Vh + buf * BN * VSTR;
        __nv_bfloat16* Vlb = Vl + buf * BN * VSTR;

        CP_WAIT1();        // oldest group (this buf) complete
        __syncthreads();   // visibility across warps

        // --- S = Q K^T  (tf32 mma, fp32 accum), BN=32 -> 4 n-tiles ---
        float s[4][4];
#pragma unroll
        for (int t = 0; t < 4; t++) { s[t][0]=0.f; s[t][1]=0.f; s[t][2]=0.f; s[t][3]=0.f; }

#pragma unroll
        for (int kk = 0; kk < DE; kk += 8) {
            uint32_t a0 = __float_as_uint(Qs[(mrow + qr    ) * QSTR + kk + qc    ]);
            uint32_t a1 = __float_as_uint(Qs[(mrow + qr + 8) * QSTR + kk + qc    ]);
            uint32_t a2 = __float_as_uint(Qs[(mrow + qr    ) * QSTR + kk + qc + 4]);
            uint32_t a3 = __float_as_uint(Qs[(mrow + qr + 8) * QSTR + kk + qc + 4]);
#pragma unroll
            for (int nt = 0; nt < 4; nt++) {
                uint32_t b0 = __float_as_uint(Kb[(nt * 8 + qr) * QSTR + kk + qc    ]);
                uint32_t b1 = __float_as_uint(Kb[(nt * 8 + qr) * QSTR + kk + qc + 4]);
                asm volatile(
                    "mma.sync.aligned.m16n8k8.row.col.f32.tf32.tf32.f32 "
                    "{%0,%1,%2,%3}, {%4,%5,%6,%7}, {%8,%9}, {%0,%1,%2,%3};"
                    : "+f"(s[nt][0]), "+f"(s[nt][1]), "+f"(s[nt][2]), "+f"(s[nt][3])
                    : "r"(a0), "r"(a1), "r"(a2), "r"(a3), "r"(b0), "r"(b1));
            }
        }

        // --- Fixed-max softmax: p = exp(s - 64). No max reduce, no rescale. ---
        uint32_t pa[4][2];
#pragma unroll
        for (int nt = 0; nt < 4; nt++) {
            float p0 = __expf(s[nt][0] - MAXS);
            float p1 = __expf(s[nt][1] - MAXS);
            float p2 = __expf(s[nt][2] - MAXS);
            float p3 = __expf(s[nt][3] - MAXS);
            __nv_bfloat162 h01; h01.x = __float2bfloat16(p0); h01.y = __float2bfloat16(p1);
            __nv_bfloat162 h23; h23.x = __float2bfloat16(p2); h23.y = __float2bfloat16(p3);
            pa[nt][0] = *(uint32_t*)&h01;
            pa[nt][1] = *(uint32_t*)&h23;
            // sum AFTER rounding so P-rounding cancels between numerator and l
            l0 += __bfloat162float(h01.x) + __bfloat162float(h01.y);
            l1 += __bfloat162float(h23.x) + __bfloat162float(h23.y);
        }

        // --- O += P @ (Vh + Vl)  (bf16 mma, fp32 accum), BN=32 -> 2 k-tiles ---
        int lr = lane & 15;
        int lc = (lane >> 4) << 3;
#pragma unroll
        for (int kt = 0; kt < 2; kt++) {
            uint32_t A0 = pa[2 * kt][0],     A1 = pa[2 * kt][1];
            uint32_t A2 = pa[2 * kt + 1][0], A3 = pa[2 * kt + 1][1];
#pragma unroll
            for (int np = 0; np < 8; np++) {
                const __nv_bfloat16* ph = Vhb + (kt * 16 + lr) * VSTR + np * 16 + lc;
                const __nv_bfloat16* pl = Vlb + (kt * 16 + lr) * VSTR + np * 16 + lc;
                uint32_t ah = (uint32_t)__cvta_generic_to_shared(ph);
                uint32_t al = (uint32_t)__cvta_generic_to_shared(pl);
                uint32_t b0, b1, b2, b3;
                asm volatile("ldmatrix.sync.aligned.m8n8.x4.trans.shared.b16 "
                             "{%0,%1,%2,%3}, [%4];"
                             : "=r"(b0), "=r"(b1), "=r"(b2), "=r"(b3) : "r"(ah));
                asm volatile(
                    "mma.sync.aligned.m16n8k16.row.col.f32.bf16.bf16.f32 "
                    "{%0,%1,%2,%3}, {%4,%5,%6,%7}, {%8,%9}, {%0,%1,%2,%3};"
                    : "+f"(o[2*np][0]), "+f"(o[2*np][1]), "+f"(o[2*np][2]), "+f"(o[2*np][3])
                    : "r"(A0), "r"(A1), "r"(A2), "r"(A3), "r"(b0), "r"(b1));
                asm volatile(
                    "mma.sync.aligned.m16n8k16.row.col.f32.bf16.bf16.f32 "
                    "{%0,%1,%2,%3}, {%4,%5,%6,%7}, {%8,%9}, {%0,%1,%2,%3};"
                    : "+f"(o[2*np+1][0]), "+f"(o[2*np+1][1]), "+f"(o[2*np+1][2]), "+f"(o[2*np+1][3])
                    : "r"(A0), "r"(A1), "r"(A2), "r"(A3), "r"(b2), "r"(b3));
                asm volatile("ldmatrix.sync.aligned.m8n8.x4.trans.shared.b16 "
                             "{%0,%1,%2,%3}, [%4];"
                             : "=r"(b0), "=r"(b1), "=r"(b2), "=r"(b3) : "r"(al));
                asm volatile(
                    "mma.sync.aligned.m16n8k16.row.col.f32.bf16.bf16.f32 "
                    "{%0,%1,%2,%3}, {%4,%5,%6,%7}, {%8,%9}, {%0,%1,%2,%3};"
                    : "+f"(o[2*np][0]), "+f"(o[2*np][1]), "+f"(o[2*np][2]), "+f"(o[2*np][3])
                    : "r"(A0), "r"(A1), "r"(A2), "r"(A3), "r"(b0), "r"(b1));
                asm volatile(
                    "mma.sync.aligned.m16n8k16.row.col.f32.bf16.bf16.f32 "
                    "{%0,%1,%2,%3}, {%4,%5,%6,%7}, {%8,%9}, {%0,%1,%2,%3};"
                    : "+f"(o[2*np+1][0]), "+f"(o[2*np+1][1]), "+f"(o[2*np+1][2]), "+f"(o[2*np+1][3])
                    : "r"(A0), "r"(A1), "r"(A2), "r"(A3), "r"(b2), "r"(b3));
            }
        }

        __syncthreads();   // all warps done with this buf before refill
        if (i + 2 < TILES_PER_SPLIT) issue_tile(buf, kb_begin + i + 2);
        else CP_COMMIT();  // keep group count aligned for wait_group
    }

    // --- Epilogue: reduce l across the 4 lanes of each row group, store ---
    l0 += __shfl_xor_sync(0xffffffffu, l0, 1);
    l0 += __shfl_xor_sync(0xffffffffu, l0, 2);
    l1 += __shfl_xor_sync(0xffffffffu, l1, 1);
    l1 += __shfl_xor_sync(0xffffffffu, l1, 2);

    int row0 = q0 + mrow + qr;
    int row1 = row0 + 8;
    float* part = g_part + sp * (NTOK * DE);
#pragma unroll
    for (int nt = 0; nt < 16; nt++) {
        int col = nt * 8 + 2 * qc;
        *(float2*)(part + row0 * DE + col) = make_float2(o[nt][0], o[nt][1]);
        *(float2*)(part + row1 * DE + col) = make_float2(o[nt][2], o[nt][3]);
    }
    if (qc == 0) {
        g_l[sp * NTOK + row0] = l0;
        g_l[sp * NTOK + row1] = l1;
    }
}

// Merge SPLIT partials per row: out = sum_s(O_s) / sum_s(l_s)  (shared fixed max)
__global__ void combine_kernel(float* __restrict__ out) {
    int idx = blockIdx.x * blockDim.x + threadIdx.x;   // row * DE + col
    if (idx >= NTOK * DE) return;
    int row = idx >> 7;
    int col = idx & 127;

    float L = 0.f, acc = 0.f;
#pragma unroll
    for (int s = 0; s < SPLIT; s++) {
        L   += g_l[s * NTOK + row];
        acc += g_part[s * (NTOK * DE) + row * DE + col];
    }
    float r = acc / L;
    if (col < DHALF) out[row * DHALF + col] = r;
    else             out[NTOK * DHALF + row * DHALF + (col - DHALF)] = r;
}

extern "C" void kernel_launch(void* const* d_in, const int* in_sizes, int n_in,
                              void* d_out, int out_size) {
    const float* mag   = (const float*)d_in[0];
    const float* phase = (const float*)d_in[1];
    float* out = (float*)d_out;

    build_qext_kernel<<<(NTOK * DHALF + 255) / 256, 256>>>(mag, phase);

    int smem_bytes = (BM * QSTR + 2 * BN * QSTR) * (int)sizeof(float)
                   + 4 * BN * VSTR * (int)sizeof(__nv_bfloat16);   // 102400
    cudaFuncSetAttribute(attn_kernel, cudaFuncAttributeMaxDynamicSharedMemorySize,
                         smem_bytes);
    dim3 grid(NTOK / BM, SPLIT);
    attn_kernel<<<grid, NTHREADS, smem_bytes>>>();

    combine_kernel<<<(NTOK * DE + 255) / 256, 256>>>(out);
}

// round 14
// speedup vs baseline: 2.4222x; 1.3805x over previous
#include <cuda_runtime.h>
#include <cuda_bf16.h>
#include <stdint.h>

#define NTOK 8192
#define DHALF 64
#define DE 128
#define BM 64
#define BN 32
#define QSTR 132   // fp32 row stride (528 B, 16B-aligned, conflict-free ldmatrix)
#define VSTR 136   // bf16 row stride
#define NTHREADS 128
#define SPLIT 8
#define TILES_PER_SPLIT (NTOK / BN / SPLIT)   // 32
#define MAXS 64.0f  // provable score bound: |s| <= D*max(mag)^2 <= 64

__device__ float g_qext[NTOK * DE];          // tf32-truncated [a|b]
__device__ __nv_bfloat16 g_vh[NTOK * DE];    // V hi
__device__ __nv_bfloat16 g_vl[NTOK * DE];    // V lo
__device__ float g_part[SPLIT * NTOK * DE];  // 32 MB partials
__device__ float g_l[SPLIT * NTOK];

#define CP_ASYNC16(dst_u32, src_ptr) \
    asm volatile("cp.async.cg.shared.global [%0], [%1], 16;" \
                 :: "r"(dst_u32), "l"(src_ptr))
#define CP_COMMIT()  asm volatile("cp.async.commit_group;")
#define CP_WAIT0()   asm volatile("cp.async.wait_group 0;")

__global__ void build_qext_kernel(const float* __restrict__ mag,
                                  const float* __restrict__ phase) {
    int i = blockIdx.x * blockDim.x + threadIdx.x;
    if (i >= NTOK * DHALF) return;
    int row = i >> 6;
    int d = i & 63;
    float m = mag[i];
    float p = phase[i];
    float s, c;
    sincosf(p, &s, &c);
    float a = m * c;
    float b = m * s;
    uint32_t ua, ub;
    asm("cvt.rna.tf32.f32 %0, %1;" : "=r"(ua) : "f"(a));
    asm("cvt.rna.tf32.f32 %0, %1;" : "=r"(ub) : "f"(b));
    g_qext[row * DE + d] = __uint_as_float(ua);
    g_qext[row * DE + DHALF + d] = __uint_as_float(ub);

    __nv_bfloat16 h = __float2bfloat16(m);
    __nv_bfloat16 l = __float2bfloat16(m - __bfloat162float(h));
    g_vh[row * DE + d] = h;
    g_vl[row * DE + d] = l;
    h = __float2bfloat16(p);
    l = __float2bfloat16(p - __bfloat162float(h));
    g_vh[row * DE + DHALF + d] = h;
    g_vl[row * DE + DHALF + d] = l;
}

__global__ __launch_bounds__(NTHREADS, 3)
void attn_kernel() {
    extern __shared__ char smem_raw[];
    float* Qs = (float*)smem_raw;                          // [BM][QSTR]
    float* Ks = Qs + BM * QSTR;                            // [BN][QSTR]
    __nv_bfloat16* Vh = (__nv_bfloat16*)(Ks + BN * QSTR);  // [BN][VSTR]
    __nv_bfloat16* Vl = Vh + BN * VSTR;                    // [BN][VSTR]

    int tid  = threadIdx.x;
    int lane = tid & 31;
    int warp = tid >> 5;
    int q0   = blockIdx.x * BM;
    int sp   = blockIdx.y;
    int mrow = warp * 16;

    int qc = lane & 3;

    int kb_begin = sp * TILES_PER_SPLIT;

    // ldmatrix source addresses (fixed per thread up to kk offset)
    uint32_t QsU = (uint32_t)__cvta_generic_to_shared(Qs);
    uint32_t KsU = (uint32_t)__cvta_generic_to_shared(Ks);
    uint32_t aAddrBase = QsU + (uint32_t)(mrow + (lane & 15)) * (QSTR * 4) + (lane & 16);
    uint32_t bAddr0Base = KsU + (uint32_t)(lane & 15) * (QSTR * 4) + (lane & 16);        // nt 0,1
    uint32_t bAddr1Base = KsU + (uint32_t)(16 + (lane & 15)) * (QSTR * 4) + (lane & 16); // nt 2,3

    auto fill_tile = [&](int kb) {
        int k0 = kb * BN;
#pragma unroll
        for (int it = 0; it < 8; it++) {
            int idx = tid + it * NTHREADS;
            int r = idx >> 5, c = idx & 31;
            uint32_t dst = (uint32_t)__cvta_generic_to_shared(Ks + r * QSTR + c * 4);
            CP_ASYNC16(dst, g_qext + (k0 + r) * DE + c * 4);
        }
#pragma unroll
        for (int it = 0; it < 4; it++) {
            int idx = tid + it * NTHREADS;
            int r = idx >> 4, c = idx & 15;
            uint32_t dh = (uint32_t)__cvta_generic_to_shared(Vh + r * VSTR + c * 8);
            uint32_t dl = (uint32_t)__cvta_generic_to_shared(Vl + r * VSTR + c * 8);
            CP_ASYNC16(dh, g_vh + (k0 + r) * DE + c * 8);
            CP_ASYNC16(dl, g_vl + (k0 + r) * DE + c * 8);
        }
        CP_COMMIT();
    };

    // Q tile once
    for (int idx = tid * 4; idx < BM * DE; idx += NTHREADS * 4) {
        int r = idx >> 7, c = idx & 127;
        float4 v = *(const float4*)(g_qext + (q0 + r) * DE + c);
        float* dst = Qs + r * QSTR + c;
        dst[0] = v.x; dst[1] = v.y; dst[2] = v.z; dst[3] = v.w;
    }
    fill_tile(kb_begin);

    float o[16][4];
#pragma unroll
    for (int i = 0; i < 16; i++)
#pragma unroll
        for (int j = 0; j < 4; j++) o[i][j] = 0.f;

    float l0 = 0.f, l1 = 0.f;

    for (int i = 0; i < TILES_PER_SPLIT; i++) {
        CP_WAIT0();
        __syncthreads();   // tile visible to all warps

        // --- S = Q K^T (tf32 mma), frags via ldmatrix ---
        float s[4][4];
#pragma unroll
        for (int t = 0; t < 4; t++) { s[t][0]=0.f; s[t][1]=0.f; s[t][2]=0.f; s[t][3]=0.f; }

#pragma unroll
        for (int kk = 0; kk < DE; kk += 8) {
            uint32_t a0, a1, a2, a3, b0, b1, b2, b3, c0, c1, c2, c3;
            asm volatile("ldmatrix.sync.aligned.m8n8.x4.shared.b16 {%0,%1,%2,%3}, [%4];"
                         : "=r"(a0), "=r"(a1), "=r"(a2), "=r"(a3)
                         : "r"(aAddrBase + kk * 4));
            asm volatile("ldmatrix.sync.aligned.m8n8.x4.shared.b16 {%0,%1,%2,%3}, [%4];"
                         : "=r"(b0), "=r"(b1), "=r"(b2), "=r"(b3)
                         : "r"(bAddr0Base + kk * 4));
            asm volatile("ldmatrix.sync.aligned.m8n8.x4.shared.b16 {%0,%1,%2,%3}, [%4];"
                         : "=r"(c0), "=r"(c1), "=r"(c2), "=r"(c3)
                         : "r"(bAddr1Base + kk * 4));
            asm volatile("mma.sync.aligned.m16n8k8.row.col.f32.tf32.tf32.f32 "
                         "{%0,%1,%2,%3}, {%4,%5,%6,%7}, {%8,%9}, {%0,%1,%2,%3};"
                         : "+f"(s[0][0]), "+f"(s[0][1]), "+f"(s[0][2]), "+f"(s[0][3])
                         : "r"(a0), "r"(a1), "r"(a2), "r"(a3), "r"(b0), "r"(b2));
            asm volatile("mma.sync.aligned.m16n8k8.row.col.f32.tf32.tf32.f32 "
                         "{%0,%1,%2,%3}, {%4,%5,%6,%7}, {%8,%9}, {%0,%1,%2,%3};"
                         : "+f"(s[1][0]), "+f"(s[1][1]), "+f"(s[1][2]), "+f"(s[1][3])
                         : "r"(a0), "r"(a1), "r"(a2), "r"(a3), "r"(b1), "r"(b3));
            asm volatile("mma.sync.aligned.m16n8k8.row.col.f32.tf32.tf32.f32 "
                         "{%0,%1,%2,%3}, {%4,%5,%6,%7}, {%8,%9}, {%0,%1,%2,%3};"
                         : "+f"(s[2][0]), "+f"(s[2][1]), "+f"(s[2][2]), "+f"(s[2][3])
                         : "r"(a0), "r"(a1), "r"(a2), "r"(a3), "r"(c0), "r"(c2));
            asm volatile("mma.sync.aligned.m16n8k8.row.col.f32.tf32.tf32.f32 "
                         "{%0,%1,%2,%3}, {%4,%5,%6,%7}, {%8,%9}, {%0,%1,%2,%3};"
                         : "+f"(s[3][0]), "+f"(s[3][1]), "+f"(s[3][2]), "+f"(s[3][3])
                         : "r"(a0), "r"(a1), "r"(a2), "r"(a3), "r"(c1), "r"(c3));
        }

        // --- fixed-max softmax (no reduce, no rescale) ---
        uint32_t pa[4][2];
#pragma unroll
        for (int nt = 0; nt < 4; nt++) {
            float p0 = __expf(s[nt][0] - MAXS);
            float p1 = __expf(s[nt][1] - MAXS);
            float p2 = __expf(s[nt][2] - MAXS);
            float p3 = __expf(s[nt][3] - MAXS);
            __nv_bfloat162 h01; h01.x = __float2bfloat16(p0); h01.y = __float2bfloat16(p1);
            __nv_bfloat162 h23; h23.x = __float2bfloat16(p2); h23.y = __float2bfloat16(p3);
            pa[nt][0] = *(uint32_t*)&h01;
            pa[nt][1] = *(uint32_t*)&h23;
            l0 += __bfloat162float(h01.x) + __bfloat162float(h01.y);
            l1 += __bfloat162float(h23.x) + __bfloat162float(h23.y);
        }

        // --- O += P @ (Vh + Vl) ---
        int lr = lane & 15;
        int lc = (lane >> 4) << 3;
#pragma unroll
        for (int kt = 0; kt < 2; kt++) {
            uint32_t A0 = pa[2 * kt][0],     A1 = pa[2 * kt][1];
            uint32_t A2 = pa[2 * kt + 1][0], A3 = pa[2 * kt + 1][1];
#pragma unroll
            for (int np = 0; np < 8; np++) {
                const __nv_bfloat16* ph = Vh + (kt * 16 + lr) * VSTR + np * 16 + lc;
                const __nv_bfloat16* pl = Vl + (kt * 16 + lr) * VSTR + np * 16 + lc;
                uint32_t ah = (uint32_t)__cvta_generic_to_shared(ph);
                uint32_t al = (uint32_t)__cvta_generic_to_shared(pl);
                uint32_t b0, b1, b2, b3;
                asm volatile("ldmatrix.sync.aligned.m8n8.x4.trans.shared.b16 "
                             "{%0,%1,%2,%3}, [%4];"
                             : "=r"(b0), "=r"(b1), "=r"(b2), "=r"(b3) : "r"(ah));
                asm volatile("mma.sync.aligned.m16n8k16.row.col.f32.bf16.bf16.f32 "
                             "{%0,%1,%2,%3}, {%4,%5,%6,%7}, {%8,%9}, {%0,%1,%2,%3};"
                             : "+f"(o[2*np][0]), "+f"(o[2*np][1]), "+f"(o[2*np][2]), "+f"(o[2*np][3])
                             : "r"(A0), "r"(A1), "r"(A2), "r"(A3), "r"(b0), "r"(b1));
                asm volatile("mma.sync.aligned.m16n8k16.row.col.f32.bf16.bf16.f32 "
                             "{%0,%1,%2,%3}, {%4,%5,%6,%7}, {%8,%9}, {%0,%1,%2,%3};"
                             : "+f"(o[2*np+1][0]), "+f"(o[2*np+1][1]), "+f"(o[2*np+1][2]), "+f"(o[2*np+1][3])
                             : "r"(A0), "r"(A1), "r"(A2), "r"(A3), "r"(b2), "r"(b3));
                asm volatile("ldmatrix.sync.aligned.m8n8.x4.trans.shared.b16 "
                             "{%0,%1,%2,%3}, [%4];"
                             : "=r"(b0), "=r"(b1), "=r"(b2), "=r"(b3) : "r"(al));
                asm volatile("mma.sync.aligned.m16n8k16.row.col.f32.bf16.bf16.f32 "
                             "{%0,%1,%2,%3}, {%4,%5,%6,%7}, {%8,%9}, {%0,%1,%2,%3};"
                             : "+f"(o[2*np][0]), "+f"(o[2*np][1]), "+f"(o[2*np][2]), "+f"(o[2*np][3])
                             : "r"(A0), "r"(A1), "r"(A2), "r"(A3), "r"(b0), "r"(b1));
                asm volatile("mma.sync.aligned.m16n8k16.row.col.f32.bf16.bf16.f32 "
                             "{%0,%1,%2,%3}, {%4,%5,%6,%7}, {%8,%9}, {%0,%1,%2,%3};"
                             : "+f"(o[2*np+1][0]), "+f"(o[2*np+1][1]), "+f"(o[2*np+1][2]), "+f"(o[2*np+1][3])
                             : "r"(A0), "r"(A1), "r"(A2), "r"(A3), "r"(b2), "r"(b3));
            }
        }

        __syncthreads();   // all warps done before refill
        if (i + 1 < TILES_PER_SPLIT) fill_tile(kb_begin + i + 1);
    }

    // --- epilogue ---
    l0 += __shfl_xor_sync(0xffffffffu, l0, 1);
    l0 += __shfl_xor_sync(0xffffffffu, l0, 2);
    l1 += __shfl_xor_sync(0xffffffffu, l1, 1);
    l1 += __shfl_xor_sync(0xffffffffu, l1, 2);

    int qr = lane >> 2;
    int row0 = q0 + mrow + qr;
    int row1 = row0 + 8;
    float* part = g_part + (size_t)sp * (NTOK * DE);
#pragma unroll
    for (int nt = 0; nt < 16; nt++) {
        int col = nt * 8 + 2 * qc;
        *(float2*)(part + row0 * DE + col) = make_float2(o[nt][0], o[nt][1]);
        *(float2*)(part + row1 * DE + col) = make_float2(o[nt][2], o[nt][3]);
    }
    if (qc == 0) {
        g_l[sp * NTOK + row0] = l0;
        g_l[sp * NTOK + row1] = l1;
    }
}

__global__ void combine_kernel(float* __restrict__ out) {
    int idx = blockIdx.x * blockDim.x + threadIdx.x;
    if (idx >= NTOK * DE) return;
    int row = idx >> 7;
    int col = idx & 127;

    float L = 0.f, acc = 0.f;
#pragma unroll
    for (int s = 0; s < SPLIT; s++) {
        L   += g_l[s * NTOK + row];
        acc += g_part[(size_t)s * (NTOK * DE) + row * DE + col];
    }
    float r = acc / L;
    if (col < DHALF) out[row * DHALF + col] = r;
    else             out[NTOK * DHALF + row * DHALF + (col - DHALF)] = r;
}

extern "C" void kernel_launch(void* const* d_in, const int* in_sizes, int n_in,
                              void* d_out, int out_size) {
    const float* mag   = (const float*)d_in[0];
    const float* phase = (const float*)d_in[1];
    float* out = (float*)d_out;

    build_qext_kernel<<<(NTOK * DHALF + 255) / 256, 256>>>(mag, phase);

    int smem_bytes = (BM * QSTR + BN * QSTR) * (int)sizeof(float)
                   + 2 * BN * VSTR * (int)sizeof(__nv_bfloat16);   // 68096
    cudaFuncSetAttribute(attn_kernel, cudaFuncAttributeMaxDynamicSharedMemorySize,
                         smem_bytes);
    dim3 grid(NTOK / BM, SPLIT);
    attn_kernel<<<grid, NTHREADS, smem_bytes>>>();

    combine_kernel<<<(NTOK * DE + 255) / 256, 256>>>(out);
}